// round 1
// baseline (speedup 1.0000x reference)
#include <cuda_runtime.h>

#define NWORDS 100000
#define NQ 50
#define NS 64

// Heads table in "quad" layout: for (q, sq) with sq = s>>2:
//   12 floats = h0[s..s+3], h1[s..s+3], h2[s..s+3]  (48B, 16B-aligned groups)
__device__ __align__(16) float g_hH[NQ * 16 * 12];
__device__ __align__(8)  float g_hr[NS];
__device__ double g_acc;

typedef unsigned long long u64;

__device__ __forceinline__ u64 bc2(float x) {
    u64 r; asm("mov.b64 %0, {%1, %1};" : "=l"(r) : "f"(x)); return r;
}
__device__ __forceinline__ u64 fma2(u64 a, u64 b, u64 c) {
    u64 d; asm("fma.rn.f32x2 %0, %1, %2, %3;" : "=l"(d) : "l"(a), "l"(b), "l"(c)); return d;
}
__device__ __forceinline__ u64 mul2(u64 a, u64 b) {
    u64 d; asm("mul.rn.f32x2 %0, %1, %2;" : "=l"(d) : "l"(a), "l"(b)); return d;
}
__device__ __forceinline__ void up2(u64 a, float& x, float& y) {
    asm("mov.b64 {%0, %1}, %2;" : "=f"(x), "=f"(y) : "l"(a));
}

// softplus(20x) = max(y,0) + log1p(exp(-|y|)), y = 20x  (matches jax logaddexp form)
__device__ __forceinline__ float sp20(float x) {
    float y = 20.0f * x;
    return fmaxf(y, 0.0f) + log1pf(expf(-fabsf(y)));
}

__global__ void setup_kernel(const float* __restrict__ hp, const float* __restrict__ hrp) {
    __shared__ float sv[NS];
    __shared__ float ssum;
    int tid = threadIdx.x;
    if (tid == 0) g_acc = 0.0;
    if (tid < NS) sv[tid] = sp20(hrp[tid]);
    __syncthreads();
    if (tid == 0) {
        float s = 0.0f;
        for (int i = 0; i < NS; i++) s += sv[i];
        ssum = fmaxf(s, 1e-12f);
    }
    __syncthreads();
    if (tid < NS) {
        g_hr[tid] = (sv[tid] / ssum + 0.001f / (float)NS) / 1.001f;
    }
    // heads: 64*50 = 3200 (s,q) cells
    for (int idx = tid; idx < NS * NQ; idx += blockDim.x) {
        int q = idx >> 6;        // 3200 = 50 * 64
        int s = idx & 63;
        const float* p = hp + ((size_t)s * NQ + q) * 3;
        float v0 = sp20(p[0]);
        float v1 = sp20(p[1]);
        float v2 = sp20(p[2]);
        float sm = fmaxf((v0 + v1) + v2, 1e-12f);
        int sq = s >> 2, r = s & 3;
        float* g = g_hH + ((size_t)q * 16 + sq) * 12;
        g[r]     = v0 / sm;
        g[4 + r] = v1 / sm;
        g[8 + r] = v2 / sm;
    }
}

// Thread = (n-pair, s-quarter).  256 threads/block -> 64 n-pairs (128 n) per block,
// each thread owns 8 s-pairs (16 heads) packed as f32x2 lanes.
__global__ __launch_bounds__(256, 2)
void cov_kernel(const float* __restrict__ tpl, const float* __restrict__ coeff) {
    __shared__ __align__(16) float sT[30 * 130];   // 10-q chunk, transposed, padded rows
    const int tid   = threadIdx.x;
    const int qt    = tid & 3;          // s-quarter 0..3
    const int nlo   = (tid >> 2) * 2;   // local n0 (0,2,...,126)
    const int nBase = blockIdx.x * 128;

    u64 prodA[8], prodB[8];
    const u64 ONE = 0x3f8000003f800000ULL;
#pragma unroll
    for (int j = 0; j < 8; j++) { prodA[j] = ONE; prodB[j] = ONE; }

#pragma unroll 1
    for (int qc = 0; qc < NQ; qc += 10) {
        if (qc) __syncthreads();
        // stage 128 rows x 30 floats, coalesced global read -> transposed smem
        for (int i = tid; i < 128 * 30; i += 256) {
            int nl = i / 30;
            int j  = i - nl * 30;
            int n  = nBase + nl;
            n = (n < NWORDS) ? n : (NWORDS - 1);
            sT[j * 130 + nl] = tpl[(size_t)n * (NQ * 3) + (size_t)(qc * 3 + j)];
        }
        __syncthreads();

#pragma unroll 2
        for (int qq = 0; qq < 10; qq++) {
            const float* tb = sT + (qq * 3) * 130 + nlo;
            float2 u0 = *(const float2*)(tb);
            float2 u1 = *(const float2*)(tb + 130);
            float2 u2 = *(const float2*)(tb + 260);
            u64 t0a = bc2(u0.x), t0b = bc2(u0.y);
            u64 t1a = bc2(u1.x), t1b = bc2(u1.y);
            u64 t2a = bc2(u2.x), t2b = bc2(u2.y);
            const ulonglong2* h =
                (const ulonglong2*)(g_hH + ((size_t)(qc + qq) * 16 + qt * 4) * 12);
#pragma unroll
            for (int j = 0; j < 4; j++) {
                ulonglong2 A = h[j * 3 + 0];   // h0 pairs (broadcast LDG.128)
                ulonglong2 B = h[j * 3 + 1];   // h1 pairs
                ulonglong2 C = h[j * 3 + 2];   // h2 pairs
                u64 a;
                a = mul2(C.x, t2a); a = fma2(B.x, t1a, a); a = fma2(A.x, t0a, a);
                prodA[2 * j]     = mul2(prodA[2 * j], a);
                a = mul2(C.x, t2b); a = fma2(B.x, t1b, a); a = fma2(A.x, t0b, a);
                prodB[2 * j]     = mul2(prodB[2 * j], a);
                a = mul2(C.y, t2a); a = fma2(B.y, t1a, a); a = fma2(A.y, t0a, a);
                prodA[2 * j + 1] = mul2(prodA[2 * j + 1], a);
                a = mul2(C.y, t2b); a = fma2(B.y, t1b, a); a = fma2(A.y, t0b, a);
                prodB[2 * j + 1] = mul2(prodB[2 * j + 1], a);
            }
        }
    }

    // ratio-weighted partial covs over this thread's 8 s-pairs
    float covA = 0.0f, covB = 0.0f;
#pragma unroll
    for (int j = 0; j < 8; j++) {
        float2 w = *(const float2*)(g_hr + (size_t)(qt * 8 + j) * 2);
        float lo, hi;
        up2(prodA[j], lo, hi);
        covA = fmaf(w.x, lo, covA); covA = fmaf(w.y, hi, covA);
        up2(prodB[j], lo, hi);
        covB = fmaf(w.x, lo, covB); covB = fmaf(w.y, hi, covB);
    }
    // combine the 4 s-quarters (lanes grouped by tid&3)
    covA += __shfl_xor_sync(0xffffffffu, covA, 1);
    covA += __shfl_xor_sync(0xffffffffu, covA, 2);
    covB += __shfl_xor_sync(0xffffffffu, covB, 1);
    covB += __shfl_xor_sync(0xffffffffu, covB, 2);

    double term = 0.0;
    int n0 = nBase + nlo;
    if (qt == 0 && n0 < NWORDS) {
        float c0 = coeff[n0];
        term = ((double)c0 * (double)c0) / (double)covA;
        if (n0 + 1 < NWORDS) {
            float c1 = coeff[n0 + 1];
            term += ((double)c1 * (double)c1) / (double)covB;
        }
    }
#pragma unroll
    for (int o = 16; o > 0; o >>= 1)
        term += __shfl_down_sync(0xffffffffu, term, o);
    if ((tid & 31) == 0) atomicAdd(&g_acc, term);
}

__global__ void fin_kernel(float* out) {
    out[0] = (float)g_acc;
}

extern "C" void kernel_launch(void* const* d_in, const int* in_sizes, int n_in,
                              void* d_out, int out_size) {
    const float* tpl = (const float*)d_in[0];   // batch_pauli_tensor [N,Q,P] f32
    const float* cf  = (const float*)d_in[1];   // batch_coeff [N]
    const float* hp  = (const float*)d_in[2];   // heads_param [S,Q,P]
    const float* hrp = (const float*)d_in[3];   // head_ratios_param [S]
    setup_kernel<<<1, 256>>>(hp, hrp);
    cov_kernel<<<(NWORDS + 127) / 128, 256>>>(tpl, cf);
    fin_kernel<<<1, 1>>>((float*)d_out);
}